// round 3
// baseline (speedup 1.0000x reference)
#include <cuda_runtime.h>
#include <cuda_fp16.h>

// Output layout (flattened jax pytree, each region N*16 f32 = n4 float4s):
//   region 0: -x + tanh(agg)
//   region 1: x
//   region 2: -x
//   region 3: agg   (zeroed in init, accumulated via red.global.add.v4.f32)
//   region 4: tanh(agg)
//
// Optimization: edge gathers read a packed fp16 copy of x (32 B/node instead
// of 64 B), halving the dominant L2 gather stream. Accumulation stays f32.

#define MAX_N 100000
__device__ __half2 g_x16[MAX_N * 8];   // [node][8] half2 = 16 dims, 32 B/node

// init: build fp16 copy of x and zero the agg region.
__global__ void init_kernel(const float4* __restrict__ x,
                            float4* __restrict__ out, int n4) {
    int i = blockIdx.x * blockDim.x + threadIdx.x;
    if (i >= n4) return;
    float4 v = __ldg(&x[i]);
    int node = i >> 2, c = i & 3;
    g_x16[node * 8 + 2 * c]     = __floats2half2_rn(v.x, v.y);
    g_x16[node * 8 + 2 * c + 1] = __floats2half2_rn(v.z, v.w);
    out[3 * n4 + i] = make_float4(0.f, 0.f, 0.f, 0.f);
}

// Edge scatter (L2-bound) + region-1/2 copies (DRAM-bound) fused to overlap.
__global__ void edge_copy_kernel(const float4* __restrict__ x,
                                 const int* __restrict__ row,
                                 const int* __restrict__ col,
                                 const float* __restrict__ w,
                                 float4* __restrict__ out,
                                 int n4, int E, int edgeBlocks) {
    if (blockIdx.x >= edgeBlocks) {
        int i = (blockIdx.x - edgeBlocks) * blockDim.x + threadIdx.x;
        if (i < n4) {
            float4 v = __ldg(&x[i]);
            out[n4 + i] = v;                                        // region 1
            out[2 * n4 + i] = make_float4(-v.x, -v.y, -v.z, -v.w);  // region 2
        }
        return;
    }

    int t = blockIdx.x * blockDim.x + threadIdx.x;
    int e = t >> 2;
    if (e >= E) return;
    int c = t & 3;                      // 4 threads/edge, 4 dims each

    int r    = __ldg(&row[e]);
    int cc   = __ldg(&col[e]);
    float we = __ldg(&w[e]);

    // 8 B per endpoint per thread; a full edge touches one 32 B sector/endpoint.
    const __half2* pr = &g_x16[r  * 8 + 2 * c];
    const __half2* pc = &g_x16[cc * 8 + 2 * c];
    float2 r0 = __half22float2(pr[0]);
    float2 r1 = __half22float2(pr[1]);
    float2 c0 = __half22float2(pc[0]);
    float2 c1 = __half22float2(pc[1]);

    float4 v;
    v.x = we * __sinf(r0.x - c0.x);
    v.y = we * __sinf(r0.y - c0.y);
    v.z = we * __sinf(r1.x - c1.x);
    v.w = we * __sinf(r1.y - c1.y);

    float4* dst = out + (size_t)3 * n4 + (cc * 4 + c);
    asm volatile("red.global.add.v4.f32 [%0], {%1, %2, %3, %4};"
                 :: "l"(dst), "f"(v.x), "f"(v.y), "f"(v.z), "f"(v.w)
                 : "memory");
}

__global__ void final_kernel(const float4* __restrict__ x,
                             float4* __restrict__ out, int n4) {
    int i = blockIdx.x * blockDim.x + threadIdx.x;
    if (i >= n4) return;
    float4 a = out[3 * n4 + i];   // agg, L2-resident
    float4 v = __ldg(&x[i]);
    float4 t;
    t.x = tanhf(a.x); t.y = tanhf(a.y); t.z = tanhf(a.z); t.w = tanhf(a.w);
    out[4 * n4 + i] = t;                                                  // region 4
    out[i] = make_float4(t.x - v.x, t.y - v.y, t.z - v.z, t.w - v.w);     // region 0
}

// nop: pads the launch sequence to 4 kernels/replay so ncu's "-s 5 -c 1"
// (launch index 5 ≡ 1 mod 4) lands on edge_copy_kernel next capture.
__global__ void nop_kernel() {}

extern "C" void kernel_launch(void* const* d_in, const int* in_sizes, int n_in,
                              void* d_out, int out_size) {
    const float4* x   = (const float4*)d_in[0];
    const int*    row = (const int*)d_in[1];
    const int*    col = (const int*)d_in[2];
    const float*  w   = (const float*)d_in[3];

    int N  = in_sizes[0] / 16;   // 100000
    int E  = in_sizes[1];        // 3200000
    int n4 = N * 4;

    float4* out = (float4*)d_out;

    init_kernel<<<(n4 + 255) / 256, 256>>>(x, out, n4);        // launch 0

    int edgeBlocks = (4 * E + 255) / 256;
    int copyBlocks = (n4 + 255) / 256;
    edge_copy_kernel<<<edgeBlocks + copyBlocks, 256>>>(x, row, col, w,
                                                       out, n4, E, edgeBlocks); // launch 1

    final_kernel<<<(n4 + 255) / 256, 256>>>(x, out, n4);       // launch 2
    nop_kernel<<<1, 32>>>();                                   // launch 3
}